// round 10
// baseline (speedup 1.0000x reference)
#include <cuda_runtime.h>
#include <cuda_bf16.h>

// GaussianSplatting2D: SINGLE kernel, no grid sync. Each block bins all N
// gaussians itself: cheap bbox test (sincos + 2 diag covariance terms) for
// all candidates, full Cholesky+sigmoid recompute only for hits.
// 512 tiles of 16x8; block = 4 partitions x 128 pixels.
// alpha = opac * ex2(-(u^2+v^2)), u = P*px + R*py + U0, v = S*py + V0.
// Exact split-transmittance combine: acc = a0 + T0*(a1 + T1*(a2 + T2*a3)).

#define IMG_W 256
#define IMG_H 256
#define TILE_W 16
#define TILE_H 8
#define TILES_X (IMG_W / TILE_W)       // 16
#define NUM_TILES 512
#define PIX (TILE_W * TILE_H)          // 128
#define NPART 4
#define THREADS (PIX * NPART)          // 512
#define MAX_N 1024
#define Q_CUT 12.0f                    // measured rel_err ~1.4e-4 (tol 1e-3)
#define LOG2E 1.4426950408889634f

__device__ __forceinline__ bool bbox_hit(const float2* means, const float* quats,
                                         const float2* scales, int i,
                                         float tx0, float tx1, float ty0, float ty1) {
    float2 mn = means[i];
    float2 sc = scales[i];
    float c, s;
    __sincosf(quats[i], &s, &c);
    float sx2 = sc.x * sc.x, sy2 = sc.y * sc.y;
    float cc = c * c, ss = s * s;
    float a11 = fmaf(cc, sx2, ss * sy2);
    float a22 = fmaf(ss, sx2, cc * sy2);
    float rx = sqrtf(Q_CUT * a11);
    float ry = sqrtf(Q_CUT * a22);
    return (mn.x - rx <= tx1) && (mn.x + rx >= tx0) &&
           (mn.y - ry <= ty1) && (mn.y + ry >= ty0);
}

__global__ void __launch_bounds__(THREADS, 4) splat_kernel(
    const float2* __restrict__ means,
    const float*  __restrict__ quats,
    const float2* __restrict__ scales,
    const float*  __restrict__ rgbs,
    const float*  __restrict__ opacities,
    float* __restrict__ out,
    int n)
{
    __shared__ float4 s0[MAX_N];   // (P, R, U0, S)
    __shared__ float4 s1[MAX_N];   // (V0, opac, opac*color, 0)
    __shared__ int    sCnt[16];
    __shared__ int    sOff[16];
    __shared__ int    sTot;
    __shared__ float2 sComb[NPART][PIX];

    int tile = blockIdx.x;
    int tid  = threadIdx.x;
    int lane = tid & 31;
    int w    = tid >> 5;
    unsigned lmask = (1u << lane) - 1u;

    int txi = tile % TILES_X;
    int tyi = tile / TILES_X;
    float tx0 = (float)(txi * TILE_W), tx1 = tx0 + (float)TILE_W;
    float ty0 = (float)(tyi * TILE_H), ty1 = ty0 + (float)TILE_H;

    // ---- Phase A1: cheap hit test for candidates 2t, 2t+1 ----
    int i0 = tid * 2;
    int i1 = i0 + 1;
    bool h0 = (i0 < n) && bbox_hit(means, quats, scales, i0, tx0, tx1, ty0, ty1);
    bool h1 = (i1 < n) && bbox_hit(means, quats, scales, i1, tx0, tx1, ty0, ty1);

    unsigned m0 = __ballot_sync(0xffffffffu, h0);
    unsigned m1 = __ballot_sync(0xffffffffu, h1);
    if (lane == 0) sCnt[w] = __popc(m0) + __popc(m1);
    __syncthreads();
    if (tid < 16) {
        int v = sCnt[tid];
        int x = v;
        #pragma unroll
        for (int d = 1; d < 16; d <<= 1) {
            int y = __shfl_up_sync(0x0000ffffu, x, d);
            if (tid >= d) x += y;
        }
        sOff[tid] = x - v;
        if (tid == 15) sTot = x;
    }
    __syncthreads();

    // ---- Phase A2: full params only for hits, written in order ----
    {
        int pre = sOff[w] + __popc(m0 & lmask) + __popc(m1 & lmask);
        #pragma unroll 2
        for (int k = 0; k < 2; k++) {
            bool h = k ? h1 : h0;
            if (h) {
                int i = k ? i1 : i0;
                int o = k ? (pre + (h0 ? 1 : 0)) : pre;
                float2 mn = means[i];
                float2 sc = scales[i];
                float c, s;
                __sincosf(quats[i], &s, &c);
                float sx2 = sc.x * sc.x, sy2 = sc.y * sc.y;
                float cc = c * c, ss = s * s, cs = c * s;
                float a11 = fmaf(cc, sx2, ss * sy2);
                float a12 = cs * (sx2 - sy2);
                float a22 = fmaf(ss, sx2, cc * sy2);
                float inv_det = 1.0f / (a11 * a22 - a12 * a12);
                float ia =  a22 * inv_det;
                float ib = -a12 * inv_det;
                float ic =  a11 * inv_det;
                float L11 = sqrtf(ia);
                float L12 = ib / L11;
                float L22 = sqrtf(ic - L12 * L12);
                float kk = sqrtf(0.5f * LOG2E);
                float P = kk * L11;
                float R = kk * L12;
                float S = kk * L22;
                float U0 = -(P * mn.x + R * mn.y);
                float V0 = -S * mn.y;
                float opac  = 1.0f / (1.0f + __expf(-opacities[i]));
                float color = 1.0f / (1.0f + __expf(-rgbs[i]));
                s0[o] = make_float4(P, R, U0, S);
                s1[o] = make_float4(V0, opac, opac * color, 0.0f);
            }
        }
    }
    __syncthreads();
    int total = sTot;

    // ---- Phase B: compositing, 4-way split ----
    int part = tid >> 7;
    int ptid = tid & (PIX - 1);
    int pxq  = txi * TILE_W + (ptid & (TILE_W - 1));
    int pyq  = tyi * TILE_H + (ptid >> 4);
    float px = (float)pxq + 0.5f;
    float py = (float)pyq + 0.5f;

    int len = (total + NPART - 1) >> 2;
    int jb  = part * len;
    int je  = jb + len;
    if (jb > total) jb = total;
    if (je > total) je = total;

    float T = 1.0f, acc = 0.0f;

    #pragma unroll 4
    for (int j = jb; j < je; j++) {
        float4 a = s0[j];
        float4 b = s1[j];
        float u = fmaf(a.x, px, fmaf(a.y, py, a.z));
        float v = fmaf(a.w, py, b.x);
        float vv = v * v;
        float q = fmaf(u, -u, -vv);     // -(u^2 + v^2)
        float e;
        asm("ex2.approx.ftz.f32 %0, %1;" : "=f"(e) : "f"(q));
        float wt = e * T;
        acc = fmaf(b.z, wt, acc);       // += color*opac*e*T
        T   = fmaf(-b.y, wt, T);        // *= (1 - opac*e)
    }

    sComb[part][ptid] = make_float2(acc, T);
    __syncthreads();

    // ---- Combine: acc = a0 + T0*(a1 + T1*(a2 + T2*a3)) ----
    if (tid < PIX) {
        float2 c0 = sComb[0][tid];
        float2 c1 = sComb[1][tid];
        float2 c2 = sComb[2][tid];
        float2 c3 = sComb[3][tid];
        float r = fmaf(c2.y, c3.x, c2.x);
        r = fmaf(c1.y, r, c1.x);
        r = fmaf(c0.y, r, c0.x);
        int opx = txi * TILE_W + (tid & (TILE_W - 1));
        int opy = tyi * TILE_H + (tid >> 4);
        out[opy * IMG_W + opx] = r;
    }
}

extern "C" void kernel_launch(void* const* d_in, const int* in_sizes, int n_in,
                              void* d_out, int out_size) {
    const float2* means     = (const float2*)d_in[0];
    const float*  quats     = (const float*)d_in[1];
    const float2* scales    = (const float2*)d_in[2];
    const float*  rgbs      = (const float*)d_in[3];
    const float*  opacities = (const float*)d_in[4];
    float* out = (float*)d_out;

    int n = in_sizes[1];
    if (n > MAX_N) n = MAX_N;

    splat_kernel<<<NUM_TILES, THREADS>>>(means, quats, scales, rgbs, opacities, out, n);
}

// round 11
// speedup vs baseline: 1.1399x; 1.1399x over previous
#include <cuda_runtime.h>
#include <cuda_bf16.h>

// GaussianSplatting2D: preprocess (Cholesky + packed tile bbox) + fused
// bin/composite render, PDL-overlapped. 512 tiles of 16x8.
// Render block = 256 threads = 4 partitions x 64 threads; each thread owns
// TWO adjacent pixels (same row) -> row terms + smem loads shared, 2 ILP chains.
// alpha = opac * ex2(-(u^2+v^2)), u = P*px + R*py + U0, v = S*py + V0.
// Exact split-transmittance combine: acc = a0 + T0*(a1 + T1*(a2 + T2*a3)).

#define IMG_W 256
#define IMG_H 256
#define TILE_W 16
#define TILE_H 8
#define TILES_X (IMG_W / TILE_W)       // 16
#define TILES_Y (IMG_H / TILE_H)       // 32
#define NUM_TILES 512
#define PIX (TILE_W * TILE_H)          // 128
#define NPART 4
#define THREADS 256                    // 4 parts x 64 threads x 2 px
#define MAX_N 1024
#define Q_CUT 12.0f                    // measured rel_err ~1.4e-4 (tol 1e-3)
#define LOG2E 1.4426950408889634f

__device__ float4   g_p0[MAX_N];   // (P, R, U0, S)
__device__ float4   g_p1[MAX_N];   // (V0, opac, opac*color, 0)
__device__ unsigned g_tbb[MAX_N];  // packed tile bbox: xmin|xmax<<8|ymin<<16|ymax<<24

__global__ void preprocess_kernel(const float2* __restrict__ means,
                                  const float*  __restrict__ quats,
                                  const float2* __restrict__ scales,
                                  const float*  __restrict__ rgbs,
                                  const float*  __restrict__ opacities,
                                  int n) {
    int i = blockIdx.x * blockDim.x + threadIdx.x;
    if (i < n) {
        float2 mn = means[i];
        float2 sc = scales[i];
        float c, s;
        __sincosf(quats[i], &s, &c);
        float sx2 = sc.x * sc.x, sy2 = sc.y * sc.y;
        float a11 = c * c * sx2 + s * s * sy2;
        float a12 = c * s * (sx2 - sy2);
        float a22 = s * s * sx2 + c * c * sy2;
        float inv_det = 1.0f / (a11 * a22 - a12 * a12);
        float ia =  a22 * inv_det;
        float ib = -a12 * inv_det;
        float ic =  a11 * inv_det;

        float L11 = sqrtf(ia);
        float L12 = ib / L11;
        float L22 = sqrtf(ic - L12 * L12);
        float k = sqrtf(0.5f * LOG2E);
        float P = k * L11;
        float R = k * L12;
        float S = k * L22;
        float U0 = -(P * mn.x + R * mn.y);
        float V0 = -S * mn.y;

        float opac  = 1.0f / (1.0f + __expf(-opacities[i]));
        float color = 1.0f / (1.0f + __expf(-rgbs[i]));

        g_p0[i] = make_float4(P, R, U0, S);
        g_p1[i] = make_float4(V0, opac, opac * color, 0.0f);

        float rx = sqrtf(Q_CUT * a11);
        float ry = sqrtf(Q_CUT * a22);
        int xmin = max((int)floorf((mn.x - rx) * (1.0f / TILE_W)), 0);
        int xmax = min((int)floorf((mn.x + rx) * (1.0f / TILE_W)), TILES_X - 1);
        int ymin = max((int)floorf((mn.y - ry) * (1.0f / TILE_H)), 0);
        int ymax = min((int)floorf((mn.y + ry) * (1.0f / TILE_H)), TILES_Y - 1);
        g_tbb[i] = (unsigned)xmin | ((unsigned)xmax << 8) |
                   ((unsigned)ymin << 16) | ((unsigned)ymax << 24);
    }
    __threadfence();
    asm volatile("griddepcontrol.launch_dependents;" ::: "memory");
}

__device__ __forceinline__ bool tbb_hit(unsigned bb, unsigned txi, unsigned tyi) {
    return (txi >= (bb & 0xffu))         && (txi <= ((bb >> 8) & 0xffu)) &&
           (tyi >= ((bb >> 16) & 0xffu)) && (tyi <= (bb >> 24));
}

__global__ void __launch_bounds__(THREADS, 6) render_kernel(float* __restrict__ out, int n) {
    __shared__ float4 s0[MAX_N];
    __shared__ float4 s1[MAX_N];
    __shared__ int    sCnt[8];
    __shared__ int    sOff[8];
    __shared__ int    sTot;
    __shared__ float2 sComb[NPART][PIX];

    asm volatile("griddepcontrol.wait;" ::: "memory");

    int tile = blockIdx.x;
    int tid  = threadIdx.x;
    int lane = tid & 31;
    int w    = tid >> 5;                  // 8 warps
    unsigned lmask = (1u << lane) - 1u;

    unsigned txi = tile % TILES_X;
    unsigned tyi = tile / TILES_X;

    // ---- Phase A: single-pass ordered quad-compaction (n <= 4*THREADS) ----
    int i0 = tid * 4;
    bool h0 = false, h1 = false, h2 = false, h3 = false;
    if (i0 < n) {
        uint4 bb4 = *reinterpret_cast<const uint4*>(&g_tbb[i0]);   // 16B aligned
        h0 = tbb_hit(bb4.x, txi, tyi);
        h1 = (i0 + 1 < n) && tbb_hit(bb4.y, txi, tyi);
        h2 = (i0 + 2 < n) && tbb_hit(bb4.z, txi, tyi);
        h3 = (i0 + 3 < n) && tbb_hit(bb4.w, txi, tyi);
    }
    unsigned m0 = __ballot_sync(0xffffffffu, h0);
    unsigned m1 = __ballot_sync(0xffffffffu, h1);
    unsigned m2 = __ballot_sync(0xffffffffu, h2);
    unsigned m3 = __ballot_sync(0xffffffffu, h3);
    if (lane == 0) sCnt[w] = __popc(m0) + __popc(m1) + __popc(m2) + __popc(m3);
    __syncthreads();
    if (tid < 8) {
        int v = sCnt[tid];
        int x = v;
        #pragma unroll
        for (int d = 1; d < 8; d <<= 1) {
            int y = __shfl_up_sync(0x000000ffu, x, d);
            if (tid >= d) x += y;
        }
        sOff[tid] = x - v;
        if (tid == 7) sTot = x;
    }
    __syncthreads();
    {
        // order: lane-major, then k within lane (global index i = 128w + 4l + k)
        int pre = sOff[w] + __popc(m0 & lmask) + __popc(m1 & lmask)
                          + __popc(m2 & lmask) + __popc(m3 & lmask);
        if (h0) { s0[pre] = g_p0[i0];     s1[pre] = g_p1[i0];     pre++; }
        if (h1) { s0[pre] = g_p0[i0 + 1]; s1[pre] = g_p1[i0 + 1]; pre++; }
        if (h2) { s0[pre] = g_p0[i0 + 2]; s1[pre] = g_p1[i0 + 2]; pre++; }
        if (h3) { s0[pre] = g_p0[i0 + 3]; s1[pre] = g_p1[i0 + 3]; }
    }
    __syncthreads();
    int total = sTot;

    // ---- Phase B: compositing, 4-way split, 2 adjacent pixels per thread ----
    int part = tid >> 6;                 // 0..3
    int pq   = tid & 63;                 // pixel-pair index
    int p0   = pq * 2;                   // row-major pixel index in tile
    int pyr  = p0 >> 4;                  // 0..7
    int pxc  = p0 & 15;                  // even column
    float px0 = (float)((int)txi * TILE_W + pxc) + 0.5f;
    float px1 = px0 + 1.0f;
    float pyf = (float)((int)tyi * TILE_H + pyr) + 0.5f;

    int len = (total + NPART - 1) >> 2;
    int jb  = part * len;
    int je  = jb + len;
    if (jb > total) jb = total;
    if (je > total) je = total;

    float T0 = 1.0f, acc0 = 0.0f;
    float T1 = 1.0f, acc1 = 0.0f;

    #pragma unroll 4
    for (int j = jb; j < je; j++) {
        float4 a = s0[j];
        float4 b = s1[j];
        float uy  = fmaf(a.y, pyf, a.z);     // R*py + U0   (shared)
        float v   = fmaf(a.w, pyf, b.x);     // S*py + V0   (shared)
        float nvv = -(v * v);
        float u0 = fmaf(a.x, px0, uy);
        float u1 = fmaf(a.x, px1, uy);
        float q0 = fmaf(u0, -u0, nvv);
        float q1 = fmaf(u1, -u1, nvv);
        float e0, e1;
        asm("ex2.approx.ftz.f32 %0, %1;" : "=f"(e0) : "f"(q0));
        asm("ex2.approx.ftz.f32 %0, %1;" : "=f"(e1) : "f"(q1));
        float wt0 = e0 * T0;
        float wt1 = e1 * T1;
        acc0 = fmaf(b.z, wt0, acc0);
        acc1 = fmaf(b.z, wt1, acc1);
        T0   = fmaf(-b.y, wt0, T0);
        T1   = fmaf(-b.y, wt1, T1);
    }

    sComb[part][p0]     = make_float2(acc0, T0);
    sComb[part][p0 + 1] = make_float2(acc1, T1);
    __syncthreads();

    // ---- Combine: acc = a0 + T0*(a1 + T1*(a2 + T2*a3)) ----
    if (tid < PIX) {
        float2 c0 = sComb[0][tid];
        float2 c1 = sComb[1][tid];
        float2 c2 = sComb[2][tid];
        float2 c3 = sComb[3][tid];
        float r = fmaf(c2.y, c3.x, c2.x);
        r = fmaf(c1.y, r, c1.x);
        r = fmaf(c0.y, r, c0.x);
        int opx = (int)txi * TILE_W + (tid & (TILE_W - 1));
        int opy = (int)tyi * TILE_H + (tid >> 4);
        out[opy * IMG_W + opx] = r;
    }
}

extern "C" void kernel_launch(void* const* d_in, const int* in_sizes, int n_in,
                              void* d_out, int out_size) {
    const float2* means     = (const float2*)d_in[0];
    const float*  quats     = (const float*)d_in[1];
    const float2* scales    = (const float2*)d_in[2];
    const float*  rgbs      = (const float*)d_in[3];
    const float*  opacities = (const float*)d_in[4];
    float* out = (float*)d_out;

    int n = in_sizes[1];
    if (n > MAX_N) n = MAX_N;

    preprocess_kernel<<<4, 256>>>(means, quats, scales, rgbs, opacities, n);

    cudaLaunchConfig_t cfg = {};
    cfg.gridDim  = dim3(NUM_TILES);
    cfg.blockDim = dim3(THREADS);
    cfg.dynamicSmemBytes = 0;
    cfg.stream = 0;
    cudaLaunchAttribute attrs[1];
    attrs[0].id = cudaLaunchAttributeProgrammaticStreamSerialization;
    attrs[0].val.programmaticStreamSerializationAllowed = 1;
    cfg.attrs = attrs;
    cfg.numAttrs = 1;
    cudaError_t e = cudaLaunchKernelEx(&cfg, render_kernel, out, n);
    if (e != cudaSuccess) {
        render_kernel<<<NUM_TILES, THREADS>>>(out, n);
    }
}

// round 12
// speedup vs baseline: 1.1672x; 1.0239x over previous
#include <cuda_runtime.h>
#include <cuda_bf16.h>

// GaussianSplatting2D: preprocess (Cholesky + packed tile bbox) + fused
// bin/composite render, PDL. 512 tiles of 16x8.
// Render block = 512 threads = 8 partitions x 64 threads; each thread owns
// TWO adjacent pixels (same row) -> shared row terms + 2 ILP chains.
// alpha = opac * ex2(-(u^2+v^2)), u = P*px + R*py + U0, v = S*py + V0.
// Exact split-transmittance combine (8-term Horner).

#define IMG_W 256
#define IMG_H 256
#define TILE_W 16
#define TILE_H 8
#define TILES_X (IMG_W / TILE_W)       // 16
#define TILES_Y (IMG_H / TILE_H)       // 32
#define NUM_TILES 512
#define PIX (TILE_W * TILE_H)          // 128
#define NPART 8
#define THREADS 512                    // 8 parts x 64 threads x 2 px
#define MAX_N 1024
#define Q_CUT 12.0f                    // measured rel_err ~1.4e-4 (tol 1e-3)
#define LOG2E 1.4426950408889634f

__device__ float4   g_p0[MAX_N];   // (P, R, U0, S)
__device__ float4   g_p1[MAX_N];   // (V0, opac, opac*color, 0)
__device__ unsigned g_tbb[MAX_N];  // packed tile bbox: xmin|xmax<<8|ymin<<16|ymax<<24

__global__ void preprocess_kernel(const float2* __restrict__ means,
                                  const float*  __restrict__ quats,
                                  const float2* __restrict__ scales,
                                  const float*  __restrict__ rgbs,
                                  const float*  __restrict__ opacities,
                                  int n) {
    int i = blockIdx.x * blockDim.x + threadIdx.x;
    if (i < n) {
        float2 mn = means[i];
        float2 sc = scales[i];
        float c, s;
        __sincosf(quats[i], &s, &c);
        float sx2 = sc.x * sc.x, sy2 = sc.y * sc.y;
        float a11 = c * c * sx2 + s * s * sy2;
        float a12 = c * s * (sx2 - sy2);
        float a22 = s * s * sx2 + c * c * sy2;
        float inv_det = 1.0f / (a11 * a22 - a12 * a12);
        float ia =  a22 * inv_det;
        float ib = -a12 * inv_det;
        float ic =  a11 * inv_det;

        float L11 = sqrtf(ia);
        float L12 = ib / L11;
        float L22 = sqrtf(ic - L12 * L12);
        float k = sqrtf(0.5f * LOG2E);
        float P = k * L11;
        float R = k * L12;
        float S = k * L22;
        float U0 = -(P * mn.x + R * mn.y);
        float V0 = -S * mn.y;

        float opac  = 1.0f / (1.0f + __expf(-opacities[i]));
        float color = 1.0f / (1.0f + __expf(-rgbs[i]));

        g_p0[i] = make_float4(P, R, U0, S);
        g_p1[i] = make_float4(V0, opac, opac * color, 0.0f);

        float rx = sqrtf(Q_CUT * a11);
        float ry = sqrtf(Q_CUT * a22);
        int xmin = max((int)floorf((mn.x - rx) * (1.0f / TILE_W)), 0);
        int xmax = min((int)floorf((mn.x + rx) * (1.0f / TILE_W)), TILES_X - 1);
        int ymin = max((int)floorf((mn.y - ry) * (1.0f / TILE_H)), 0);
        int ymax = min((int)floorf((mn.y + ry) * (1.0f / TILE_H)), TILES_Y - 1);
        g_tbb[i] = (unsigned)xmin | ((unsigned)xmax << 8) |
                   ((unsigned)ymin << 16) | ((unsigned)ymax << 24);
    }
    __threadfence();
    asm volatile("griddepcontrol.launch_dependents;" ::: "memory");
}

__device__ __forceinline__ bool tbb_hit(unsigned bb, unsigned txi, unsigned tyi) {
    return (txi >= (bb & 0xffu))         && (txi <= ((bb >> 8) & 0xffu)) &&
           (tyi >= ((bb >> 16) & 0xffu)) && (tyi <= (bb >> 24));
}

__global__ void __launch_bounds__(THREADS, 3) render_kernel(float* __restrict__ out, int n) {
    __shared__ float4 s0[MAX_N];
    __shared__ float4 s1[MAX_N];
    __shared__ int    sCnt[16];
    __shared__ int    sOff[16];
    __shared__ int    sTot;
    __shared__ float2 sComb[NPART][PIX];

    asm volatile("griddepcontrol.wait;" ::: "memory");

    int tile = blockIdx.x;
    int tid  = threadIdx.x;
    int lane = tid & 31;
    int w    = tid >> 5;                  // 16 warps
    unsigned lmask = (1u << lane) - 1u;

    unsigned txi = tile % TILES_X;
    unsigned tyi = tile / TILES_X;

    // ---- Phase A: single-pass ordered pair-compaction (n <= 2*THREADS) ----
    int i0 = tid * 2;
    int i1 = i0 + 1;
    bool h0 = false, h1 = false;
    if (i0 < n) {
        uint2 bb2 = *reinterpret_cast<const uint2*>(&g_tbb[i0]);   // 8B aligned
        h0 = tbb_hit(bb2.x, txi, tyi);
        h1 = (i1 < n) && tbb_hit(bb2.y, txi, tyi);
    }
    unsigned m0 = __ballot_sync(0xffffffffu, h0);
    unsigned m1 = __ballot_sync(0xffffffffu, h1);
    if (lane == 0) sCnt[w] = __popc(m0) + __popc(m1);
    __syncthreads();
    if (tid < 16) {
        int v = sCnt[tid];
        int x = v;
        #pragma unroll
        for (int d = 1; d < 16; d <<= 1) {
            int y = __shfl_up_sync(0x0000ffffu, x, d);
            if (tid >= d) x += y;
        }
        sOff[tid] = x - v;
        if (tid == 15) sTot = x;
    }
    __syncthreads();
    {
        int pre = sOff[w] + __popc(m0 & lmask) + __popc(m1 & lmask);
        if (h0) { s0[pre] = g_p0[i0]; s1[pre] = g_p1[i0]; pre++; }
        if (h1) { s0[pre] = g_p0[i1]; s1[pre] = g_p1[i1]; }
    }
    __syncthreads();
    int total = sTot;

    // ---- Phase B: compositing, 8-way split, 2 adjacent pixels per thread ----
    int part = tid >> 6;                 // 0..7
    int pq   = tid & 63;                 // pixel-pair index
    int p0   = pq * 2;                   // row-major pixel index in tile
    int pyr  = p0 >> 4;                  // 0..7
    int pxc  = p0 & 15;                  // even column
    float px0 = (float)((int)txi * TILE_W + pxc) + 0.5f;
    float px1 = px0 + 1.0f;
    float pyf = (float)((int)tyi * TILE_H + pyr) + 0.5f;

    int len = (total + NPART - 1) >> 3;
    int jb  = min(part * len, total);
    int je  = min(jb + len, total);

    float T0 = 1.0f, acc0 = 0.0f;
    float T1 = 1.0f, acc1 = 0.0f;

    #pragma unroll 4
    for (int j = jb; j < je; j++) {
        float4 a = s0[j];
        float4 b = s1[j];
        float uy  = fmaf(a.y, pyf, a.z);     // R*py + U0   (shared)
        float v   = fmaf(a.w, pyf, b.x);     // S*py + V0   (shared)
        float nvv = -(v * v);
        float u0 = fmaf(a.x, px0, uy);
        float u1 = fmaf(a.x, px1, uy);
        float q0 = fmaf(u0, -u0, nvv);
        float q1 = fmaf(u1, -u1, nvv);
        float e0, e1;
        asm("ex2.approx.ftz.f32 %0, %1;" : "=f"(e0) : "f"(q0));
        asm("ex2.approx.ftz.f32 %0, %1;" : "=f"(e1) : "f"(q1));
        float wt0 = e0 * T0;
        float wt1 = e1 * T1;
        acc0 = fmaf(b.z, wt0, acc0);
        acc1 = fmaf(b.z, wt1, acc1);
        T0   = fmaf(-b.y, wt0, T0);
        T1   = fmaf(-b.y, wt1, T1);
    }

    sComb[part][p0]     = make_float2(acc0, T0);
    sComb[part][p0 + 1] = make_float2(acc1, T1);
    __syncthreads();

    // ---- Combine: 8-term Horner, front-to-back ----
    if (tid < PIX) {
        float2 c7 = sComb[7][tid];
        float r = c7.x;
        #pragma unroll
        for (int p = 6; p >= 0; p--) {
            float2 cp = sComb[p][tid];
            r = fmaf(cp.y, r, cp.x);
        }
        int opx = (int)txi * TILE_W + (tid & (TILE_W - 1));
        int opy = (int)tyi * TILE_H + (tid >> 4);
        out[opy * IMG_W + opx] = r;
    }
}

extern "C" void kernel_launch(void* const* d_in, const int* in_sizes, int n_in,
                              void* d_out, int out_size) {
    const float2* means     = (const float2*)d_in[0];
    const float*  quats     = (const float*)d_in[1];
    const float2* scales    = (const float2*)d_in[2];
    const float*  rgbs      = (const float*)d_in[3];
    const float*  opacities = (const float*)d_in[4];
    float* out = (float*)d_out;

    int n = in_sizes[1];
    if (n > MAX_N) n = MAX_N;

    preprocess_kernel<<<4, 256>>>(means, quats, scales, rgbs, opacities, n);

    cudaLaunchConfig_t cfg = {};
    cfg.gridDim  = dim3(NUM_TILES);
    cfg.blockDim = dim3(THREADS);
    cfg.dynamicSmemBytes = 0;
    cfg.stream = 0;
    cudaLaunchAttribute attrs[1];
    attrs[0].id = cudaLaunchAttributeProgrammaticStreamSerialization;
    attrs[0].val.programmaticStreamSerializationAllowed = 1;
    cfg.attrs = attrs;
    cfg.numAttrs = 1;
    cudaError_t e = cudaLaunchKernelEx(&cfg, render_kernel, out, n);
    if (e != cudaSuccess) {
        render_kernel<<<NUM_TILES, THREADS>>>(out, n);
    }
}